// round 8
// baseline (speedup 1.0000x reference)
#include <cuda_runtime.h>
#include <cuda_fp16.h>
#include <math.h>
#include <stdint.h>

#define N_WORD 50000
#define N_DOC  10000
#define E_WW   800000
#define E_WD   320000

// ---------------- device scratch (static allocation only) ----------------
__device__ __half g_twn[(size_t)N_WORD * 384];  // [t_ww | t_wwr | t_wd] per word
__device__ float  g_tws[(size_t)N_WORD * 128];  // combined self transform (word)
__device__ __half g_tdn[(size_t)N_DOC * 128];   // t_wdr per doc
__device__ float  g_tds[(size_t)N_DOC * 128];   // self transform (doc)
__device__ float  g_xw[(size_t)N_WORD * 128];   // layer-1 word output
__device__ float  g_xd[(size_t)N_DOC * 128];    // layer-1 doc output
__device__ float  g_Bw[256 * 512];              // concat word weights  L1
__device__ float  g_Bd[256 * 256];              // concat doc weights   L1
__device__ float  g_Bw2[128 * 512];             // concat word weights  L2
__device__ float  g_Bd2[128 * 256];             // concat doc weights   L2

// CSR per relation: 0=ww, 1=wwr, 2=wd(dst=doc), 3=wdr
__device__ int g_ptr_ww[N_WORD + 1], g_ptr_wwr[N_WORD + 1], g_ptr_wdr[N_WORD + 1];
__device__ int g_ptr_wd[N_DOC + 1];
__device__ int g_cur_ww[N_WORD + 1], g_cur_wwr[N_WORD + 1], g_cur_wdr[N_WORD + 1];
__device__ int g_cur_wd[N_DOC + 1];
__device__ int g_col_ww[E_WW], g_col_wwr[E_WW], g_col_wd[E_WD], g_col_wdr[E_WD];

__device__ __forceinline__ int* cur_of(int rel) {
    switch (rel) { case 0: return g_cur_ww; case 1: return g_cur_wwr;
                   case 2: return g_cur_wd; default: return g_cur_wdr; }
}
__device__ __forceinline__ int* ptr_of(int rel) {
    switch (rel) { case 0: return g_ptr_ww; case 1: return g_ptr_wwr;
                   case 2: return g_ptr_wd; default: return g_ptr_wdr; }
}

// ---------------- CSR build ----------------
__global__ void zero_cnt_kernel() {
    int i = blockIdx.x * blockDim.x + threadIdx.x;
    if (i < N_WORD + 1) { g_cur_ww[i] = 0; g_cur_wwr[i] = 0; g_cur_wdr[i] = 0; }
    if (i < N_DOC + 1)  { g_cur_wd[i] = 0; }
}

__global__ void hist_all_kernel(const int* __restrict__ ww_dst, const int* __restrict__ wwr_dst,
                                const int* __restrict__ wd_dst, const int* __restrict__ wdr_dst) {
    const int total = 2 * E_WW + 2 * E_WD;
    for (int i = blockIdx.x * blockDim.x + threadIdx.x; i < total; i += gridDim.x * blockDim.x) {
        if (i < E_WW)                  atomicAdd(&g_cur_ww[ww_dst[i]], 1);
        else if (i < 2 * E_WW)         atomicAdd(&g_cur_wwr[wwr_dst[i - E_WW]], 1);
        else if (i < 2 * E_WW + E_WD)  atomicAdd(&g_cur_wd[wd_dst[i - 2 * E_WW]], 1);
        else                           atomicAdd(&g_cur_wdr[wdr_dst[i - 2 * E_WW - E_WD]], 1);
    }
}

__global__ void scan_all_kernel() {
    int rel = blockIdx.x;
    int n = (rel == 2) ? N_DOC : N_WORD;
    int* cnt = cur_of(rel);
    int* ptr = ptr_of(rel);
    __shared__ int sh_warp[32];
    __shared__ int sh_carry;
    if (threadIdx.x == 0) sh_carry = 0;
    __syncthreads();
    for (int base = 0; base < n; base += 1024) {
        int i = base + (int)threadIdx.x;
        int v = (i < n) ? cnt[i] : 0;
        int lane = threadIdx.x & 31, wid = threadIdx.x >> 5;
        int x = v;
        #pragma unroll
        for (int o = 1; o < 32; o <<= 1) { int y = __shfl_up_sync(0xffffffffu, x, o); if (lane >= o) x += y; }
        if (lane == 31) sh_warp[wid] = x;
        __syncthreads();
        if (wid == 0) {
            int s = sh_warp[lane];
            #pragma unroll
            for (int o = 1; o < 32; o <<= 1) { int y = __shfl_up_sync(0xffffffffu, s, o); if (lane >= o) s += y; }
            sh_warp[lane] = s;
        }
        __syncthreads();
        int pre = (wid > 0) ? sh_warp[wid - 1] : 0;
        int incl = x + pre + sh_carry;
        if (i < n) { int excl = incl - v; ptr[i] = excl; cnt[i] = excl; }
        __syncthreads();
        if (threadIdx.x == 1023) sh_carry = incl;
        __syncthreads();
    }
    if (threadIdx.x == 0) { ptr[n] = sh_carry; cnt[n] = sh_carry; }
}

__global__ void scatter_all_kernel(const int* __restrict__ ww_src, const int* __restrict__ ww_dst,
                                   const int* __restrict__ wwr_src, const int* __restrict__ wwr_dst,
                                   const int* __restrict__ wd_src, const int* __restrict__ wd_dst,
                                   const int* __restrict__ wdr_src, const int* __restrict__ wdr_dst) {
    const int total = 2 * E_WW + 2 * E_WD;
    for (int i = blockIdx.x * blockDim.x + threadIdx.x; i < total; i += gridDim.x * blockDim.x) {
        if (i < E_WW) {
            int p = atomicAdd(&g_cur_ww[ww_dst[i]], 1);  g_col_ww[p] = ww_src[i];
        } else if (i < 2 * E_WW) {
            int j = i - E_WW;
            int p = atomicAdd(&g_cur_wwr[wwr_dst[j]], 1); g_col_wwr[p] = wwr_src[j];
        } else if (i < 2 * E_WW + E_WD) {
            int j = i - 2 * E_WW;
            int p = atomicAdd(&g_cur_wd[wd_dst[j]], 1);   g_col_wd[p] = wd_src[j];
        } else {
            int j = i - 2 * E_WW - E_WD;
            int p = atomicAdd(&g_cur_wdr[wdr_dst[j]], 1); g_col_wdr[p] = wdr_src[j];
        }
    }
}

// ---------------- weight concat prep ----------------
__global__ void prep_w_kernel(const float* __restrict__ Ws, const float* __restrict__ Wn,
                              int K, int dst) {
    int i = blockIdx.x * blockDim.x + threadIdx.x;
    if (i >= K * 128) return;
    int k = i / 128, n = i % 128;
    int KN = K * 128;
    float* B = dst ? g_Bw2 : g_Bw;
    B[k * 512 + n]       = Wn[0 * KN + k * 128 + n];
    B[k * 512 + 128 + n] = Wn[1 * KN + k * 128 + n];
    B[k * 512 + 256 + n] = Wn[2 * KN + k * 128 + n];
    B[k * 512 + 384 + n] = Ws[0 * KN + k * 128 + n] + Ws[1 * KN + k * 128 + n]
                         + Ws[3 * KN + k * 128 + n];
}
__global__ void prep_d_kernel(const float* __restrict__ Ws, const float* __restrict__ Wn,
                              int K, int dst) {
    int i = blockIdx.x * blockDim.x + threadIdx.x;
    if (i >= K * 128) return;
    int k = i / 128, n = i % 128;
    int KN = K * 128;
    float* B = dst ? g_Bd2 : g_Bd;
    B[k * 256 + n]       = Wn[3 * KN + k * 128 + n];
    B[k * 256 + 128 + n] = Ws[2 * KN + k * 128 + n];
}

// ---------------- tf32 tensor-core GEMM, cp.async double-buffered ----------------
#define BM 128
#define BN 128
#define BK 16
#define ASTRIDE 20    // As[m][k] padded: conflict-free frag loads
#define BSTRIDE 136   // Bs[k][n] padded: conflict-free frag loads

__device__ __forceinline__ void cp16(void* smem, const void* g, bool v) {
    uint32_t sa = (uint32_t)__cvta_generic_to_shared(smem);
    int sz = v ? 16 : 0;
    asm volatile("cp.async.cg.shared.global [%0], [%1], 16, %2;" :: "r"(sa), "l"(g), "r"(sz));
}
__device__ __forceinline__ void cp_commit() {
    asm volatile("cp.async.commit_group;");
}
template <int NN>
__device__ __forceinline__ void cp_wait() {
    asm volatile("cp.async.wait_group %0;" :: "n"(NN));
}

// a_sel: 0 ext, 1 g_xw, 2 g_xd ; b_sel: 0 g_Bw,1 g_Bd,2 g_Bw2,3 g_Bd2 ; c_sel: 0 word,1 doc
__global__ __launch_bounds__(256) void gemm_tf32_kernel(const float* __restrict__ a_ext,
                                                        int a_sel, int b_sel, int c_sel,
                                                        int M, int K, int N) {
    const float* A = (a_sel == 0) ? a_ext : (a_sel == 1 ? (const float*)g_xw : (const float*)g_xd);
    const float* B = (b_sel == 0) ? (const float*)g_Bw : (b_sel == 1 ? (const float*)g_Bd
                    : (b_sel == 2 ? (const float*)g_Bw2 : (const float*)g_Bd2));

    __shared__ float As[2][BM][ASTRIDE];
    __shared__ float Bs[2][BK][BSTRIDE];

    const int tid = threadIdx.x;
    const int warp = tid >> 5, lane = tid & 31;
    const int g = lane >> 2, t = lane & 3;
    const int wm0 = (warp & 1) * 64;
    const int wn0 = (warp >> 1) * 32;
    const int row0 = blockIdx.y * BM, col0 = blockIdx.x * BN;

    float c[4][4][4];
    #pragma unroll
    for (int i = 0; i < 4; ++i)
        #pragma unroll
        for (int j = 0; j < 4; ++j)
            #pragma unroll
            for (int r = 0; r < 4; ++r) c[i][j][r] = 0.0f;

    const int ar = tid >> 2;          // 0..63
    const int ako = (tid & 3) * 4;    // 0,4,8,12
    const int brr = tid >> 4;         // 0..15
    const int bcc = (tid & 15) * 8;   // 0..120

    const int nk = K / BK;

    // prologue: stage 0
    {
        #pragma unroll
        for (int h = 0; h < 2; ++h) {
            int r = ar + h * 64;
            int gr = row0 + r;
            cp16(&As[0][r][ako], A + (size_t)gr * K + ako, gr < M);
        }
        cp16(&Bs[0][brr][bcc],     B + (size_t)brr * N + col0 + bcc, true);
        cp16(&Bs[0][brr][bcc + 4], B + (size_t)brr * N + col0 + bcc + 4, true);
        cp_commit();
    }

    for (int kt = 0; kt < nk; ++kt) {
        int cur = kt & 1;
        if (kt + 1 < nk) {
            int nxt = (kt + 1) & 1;
            int k0 = (kt + 1) * BK;
            #pragma unroll
            for (int h = 0; h < 2; ++h) {
                int r = ar + h * 64;
                int gr = row0 + r;
                cp16(&As[nxt][r][ako], A + (size_t)gr * K + k0 + ako, gr < M);
            }
            cp16(&Bs[nxt][brr][bcc],     B + (size_t)(k0 + brr) * N + col0 + bcc, true);
            cp16(&Bs[nxt][brr][bcc + 4], B + (size_t)(k0 + brr) * N + col0 + bcc + 4, true);
        }
        cp_commit();
        cp_wait<1>();
        __syncthreads();

        #pragma unroll
        for (int kk = 0; kk < BK; kk += 8) {
            uint32_t af[4][4], bf[4][2];
            #pragma unroll
            for (int i = 0; i < 4; ++i) {
                int r = wm0 + i * 16 + g;
                af[i][0] = __float_as_uint(As[cur][r][kk + t]);
                af[i][1] = __float_as_uint(As[cur][r + 8][kk + t]);
                af[i][2] = __float_as_uint(As[cur][r][kk + t + 4]);
                af[i][3] = __float_as_uint(As[cur][r + 8][kk + t + 4]);
            }
            #pragma unroll
            for (int j = 0; j < 4; ++j) {
                int cc = wn0 + j * 8 + g;
                bf[j][0] = __float_as_uint(Bs[cur][kk + t][cc]);
                bf[j][1] = __float_as_uint(Bs[cur][kk + t + 4][cc]);
            }
            #pragma unroll
            for (int i = 0; i < 4; ++i)
                #pragma unroll
                for (int j = 0; j < 4; ++j) {
                    asm volatile(
                        "mma.sync.aligned.m16n8k8.row.col.f32.tf32.tf32.f32 "
                        "{%0,%1,%2,%3}, {%4,%5,%6,%7}, {%8,%9}, {%0,%1,%2,%3};"
                        : "+f"(c[i][j][0]), "+f"(c[i][j][1]), "+f"(c[i][j][2]), "+f"(c[i][j][3])
                        : "r"(af[i][0]), "r"(af[i][1]), "r"(af[i][2]), "r"(af[i][3]),
                          "r"(bf[j][0]), "r"(bf[j][1]));
                }
        }
        __syncthreads();
    }

    const int self0 = (c_sel == 0) ? 384 : 128;
    __half* HN = (c_sel == 0) ? g_twn : g_tdn;
    float*  FS = (c_sel == 0) ? g_tws : g_tds;
    const int hn_stride = self0;

    #pragma unroll
    for (int i = 0; i < 4; ++i) {
        #pragma unroll
        for (int hrow = 0; hrow < 2; ++hrow) {
            int r = row0 + wm0 + i * 16 + g + hrow * 8;
            if (r >= M) continue;
            #pragma unroll
            for (int j = 0; j < 4; ++j) {
                int cc = col0 + wn0 + j * 8 + 2 * t;
                float v0 = c[i][j][hrow * 2 + 0], v1 = c[i][j][hrow * 2 + 1];
                if (cc < self0) {
                    *reinterpret_cast<__half2*>(HN + (size_t)r * hn_stride + cc) =
                        __float22half2_rn(make_float2(v0, v1));
                } else {
                    *reinterpret_cast<float2*>(FS + (size_t)r * 128 + (cc - self0)) =
                        make_float2(v0, v1);
                }
            }
        }
    }
}

// ---------------- aggregation + combine ----------------
__device__ __forceinline__ void acc_h4(float4& acc, const __half* __restrict__ p) {
    uint2 u = *reinterpret_cast<const uint2*>(p);
    __half2 h0 = *reinterpret_cast<const __half2*>(&u.x);
    __half2 h1 = *reinterpret_cast<const __half2*>(&u.y);
    float2 a = __half22float2(h0);
    float2 b = __half22float2(h1);
    acc.x += a.x; acc.y += a.y; acc.z += b.x; acc.w += b.y;
}

__device__ __forceinline__ float4 gather_mean_h(const __half* __restrict__ t, int stride, int base,
                                                const int* __restrict__ ptr,
                                                const int* __restrict__ col, int v, int c4) {
    int beg = ptr[v], end = ptr[v + 1];
    float4 a0 = make_float4(0.f, 0.f, 0.f, 0.f);
    float4 a1 = make_float4(0.f, 0.f, 0.f, 0.f);
    float4 a2 = make_float4(0.f, 0.f, 0.f, 0.f);
    float4 a3 = make_float4(0.f, 0.f, 0.f, 0.f);
    int e = beg;
    for (; e + 4 <= end; e += 4) {
        int s0 = col[e], s1 = col[e + 1], s2 = col[e + 2], s3 = col[e + 3];
        acc_h4(a0, t + (size_t)s0 * stride + base + c4);
        acc_h4(a1, t + (size_t)s1 * stride + base + c4);
        acc_h4(a2, t + (size_t)s2 * stride + base + c4);
        acc_h4(a3, t + (size_t)s3 * stride + base + c4);
    }
    for (; e < end; ++e) {
        int s = col[e];
        acc_h4(a0, t + (size_t)s * stride + base + c4);
    }
    a0.x += a1.x + a2.x + a3.x;
    a0.y += a1.y + a2.y + a3.y;
    a0.z += a1.z + a2.z + a3.z;
    a0.w += a1.w + a2.w + a3.w;
    int d = end - beg;
    float inv = 1.0f / (float)(d > 0 ? d : 1);
    a0.x *= inv; a0.y *= inv; a0.z *= inv; a0.w *= inv;
    return a0;
}

template <bool FINAL>
__global__ void combine_word_kernel(const float* __restrict__ b,
                                    const float* __restrict__ lin_w,
                                    const float* __restrict__ lin_b,
                                    float* __restrict__ out) {
    int warp = (blockIdx.x * blockDim.x + threadIdx.x) >> 5;
    if (warp >= N_WORD) return;
    int lane = threadIdx.x & 31;
    int c4 = lane * 4;
    int v = warp;

    float4 h = *reinterpret_cast<const float4*>(g_tws + (size_t)v * 128 + c4);
    float4 m0 = gather_mean_h(g_twn, 384, 0,   g_ptr_ww,  g_col_ww,  v, c4);
    float4 m1 = gather_mean_h(g_twn, 384, 128, g_ptr_wwr, g_col_wwr, v, c4);
    float4 m3 = gather_mean_h(g_tdn, 128, 0,   g_ptr_wdr, g_col_wdr, v, c4);

    h.x = fmaxf(h.x + m0.x + m1.x + m3.x + b[c4 + 0] + b[128 + c4 + 0] + b[384 + c4 + 0], 0.f);
    h.y = fmaxf(h.y + m0.y + m1.y + m3.y + b[c4 + 1] + b[128 + c4 + 1] + b[384 + c4 + 1], 0.f);
    h.z = fmaxf(h.z + m0.z + m1.z + m3.z + b[c4 + 2] + b[128 + c4 + 2] + b[384 + c4 + 2], 0.f);
    h.w = fmaxf(h.w + m0.w + m1.w + m3.w + b[c4 + 3] + b[128 + c4 + 3] + b[384 + c4 + 3], 0.f);

    if (!FINAL) {
        *reinterpret_cast<float4*>(g_xw + (size_t)v * 128 + c4) = h;
    } else {
        float4 lw = *reinterpret_cast<const float4*>(lin_w + c4);
        float p = h.x * lw.x + h.y * lw.y + h.z * lw.z + h.w * lw.w;
        #pragma unroll
        for (int o = 16; o > 0; o >>= 1) p += __shfl_down_sync(0xffffffffu, p, o);
        if (lane == 0) out[v] = 1.0f / (1.0f + expf(-(p + lin_b[0])));
    }
}

template <bool FINAL>
__global__ void combine_doc_kernel(const float* __restrict__ b,
                                   const float* __restrict__ lin_w,
                                   const float* __restrict__ lin_b,
                                   float* __restrict__ out) {
    int warp = (blockIdx.x * blockDim.x + threadIdx.x) >> 5;
    if (warp >= N_DOC) return;
    int lane = threadIdx.x & 31;
    int c4 = lane * 4;
    int v = warp;

    float4 h = *reinterpret_cast<const float4*>(g_tds + (size_t)v * 128 + c4);
    float4 m2 = gather_mean_h(g_twn, 384, 256, g_ptr_wd, g_col_wd, v, c4);

    h.x = fmaxf(h.x + m2.x + b[256 + c4 + 0], 0.f);
    h.y = fmaxf(h.y + m2.y + b[256 + c4 + 1], 0.f);
    h.z = fmaxf(h.z + m2.z + b[256 + c4 + 2], 0.f);
    h.w = fmaxf(h.w + m2.w + b[256 + c4 + 3], 0.f);

    if (!FINAL) {
        *reinterpret_cast<float4*>(g_xd + (size_t)v * 128 + c4) = h;
    } else {
        float4 lw = *reinterpret_cast<const float4*>(lin_w + c4);
        float p = h.x * lw.x + h.y * lw.y + h.z * lw.z + h.w * lw.w;
        #pragma unroll
        for (int o = 16; o > 0; o >>= 1) p += __shfl_down_sync(0xffffffffu, p, o);
        if (lane == 0) out[N_WORD + v] = 1.0f / (1.0f + expf(-(p + lin_b[0])));
    }
}

// ---------------- host launch ----------------
extern "C" void kernel_launch(void* const* d_in, const int* in_sizes, int n_in,
                              void* d_out, int out_size) {
    const float* x_word  = (const float*)d_in[0];
    const float* x_doc   = (const float*)d_in[1];
    const int*   ww_src  = (const int*)d_in[2];
    const int*   ww_dst  = (const int*)d_in[3];
    const int*   wwr_src = (const int*)d_in[4];
    const int*   wwr_dst = (const int*)d_in[5];
    const int*   wd_src  = (const int*)d_in[6];
    const int*   wd_dst  = (const int*)d_in[7];
    const int*   wdr_src = (const int*)d_in[8];
    const int*   wdr_dst = (const int*)d_in[9];
    const float* Wself1  = (const float*)d_in[10];
    const float* Wneigh1 = (const float*)d_in[11];
    const float* b1      = (const float*)d_in[12];
    const float* Wself2  = (const float*)d_in[13];
    const float* Wneigh2 = (const float*)d_in[14];
    const float* b2      = (const float*)d_in[15];
    const float* lin_w   = (const float*)d_in[16];
    const float* lin_b   = (const float*)d_in[17];
    float* out = (float*)d_out;

    static cudaStream_t s_csr = nullptr, s_doc = nullptr;
    static cudaEvent_t ev_fork, ev_csr, ev_w1, ev_d1, ev_wc1, ev_dc1, ev_w2, ev_d2, ev_ddone;
    if (s_csr == nullptr) {
        cudaStreamCreateWithFlags(&s_csr, cudaStreamNonBlocking);
        cudaStreamCreateWithFlags(&s_doc, cudaStreamNonBlocking);
        cudaEventCreateWithFlags(&ev_fork, cudaEventDisableTiming);
        cudaEventCreateWithFlags(&ev_csr, cudaEventDisableTiming);
        cudaEventCreateWithFlags(&ev_w1, cudaEventDisableTiming);
        cudaEventCreateWithFlags(&ev_d1, cudaEventDisableTiming);
        cudaEventCreateWithFlags(&ev_wc1, cudaEventDisableTiming);
        cudaEventCreateWithFlags(&ev_dc1, cudaEventDisableTiming);
        cudaEventCreateWithFlags(&ev_w2, cudaEventDisableTiming);
        cudaEventCreateWithFlags(&ev_d2, cudaEventDisableTiming);
        cudaEventCreateWithFlags(&ev_ddone, cudaEventDisableTiming);
    }

    // fork
    cudaEventRecord(ev_fork, 0);
    cudaStreamWaitEvent(s_csr, ev_fork, 0);
    cudaStreamWaitEvent(s_doc, ev_fork, 0);

    // CSR stream: layer-2 weight prep (independent buffers) + CSR build
    prep_w_kernel<<<(128 * 128 + 255) / 256, 256, 0, s_csr>>>(Wself2, Wneigh2, 128, 1);
    prep_d_kernel<<<(128 * 128 + 255) / 256, 256, 0, s_csr>>>(Wself2, Wneigh2, 128, 1);
    zero_cnt_kernel<<<(N_WORD + 256) / 256, 256, 0, s_csr>>>();
    hist_all_kernel<<<1184, 256, 0, s_csr>>>(ww_dst, wwr_dst, wd_dst, wdr_dst);
    scan_all_kernel<<<4, 1024, 0, s_csr>>>();
    scatter_all_kernel<<<1184, 256, 0, s_csr>>>(ww_src, ww_dst, wwr_src, wwr_dst,
                                                wd_src, wd_dst, wdr_src, wdr_dst);
    cudaEventRecord(ev_csr, s_csr);

    // doc stream: prep_d1, gemm_d1
    prep_d_kernel<<<(256 * 128 + 255) / 256, 256, 0, s_doc>>>(Wself1, Wneigh1, 256, 0);
    gemm_tf32_kernel<<<dim3(2, (N_DOC + BM - 1) / BM), 256, 0, s_doc>>>(x_doc, 0, 1, 1, N_DOC, 256, 256);
    cudaEventRecord(ev_d1, s_doc);

    // word stream (0): prep_w1, gemm_w1
    prep_w_kernel<<<(256 * 128 + 255) / 256, 256>>>(Wself1, Wneigh1, 256, 0);
    gemm_tf32_kernel<<<dim3(4, (N_WORD + BM - 1) / BM), 256>>>(x_word, 0, 0, 0, N_WORD, 256, 512);
    cudaEventRecord(ev_w1, 0);

    // word L1 combine (needs w1, d1, csr)
    cudaStreamWaitEvent(0, ev_d1, 0);
    cudaStreamWaitEvent(0, ev_csr, 0);
    combine_word_kernel<false><<<(N_WORD + 7) / 8, 256>>>(b1, lin_w, lin_b, out);
    cudaEventRecord(ev_wc1, 0);

    // doc L1 combine (needs w1, d1, csr)
    cudaStreamWaitEvent(s_doc, ev_w1, 0);
    cudaStreamWaitEvent(s_doc, ev_csr, 0);
    combine_doc_kernel<false><<<(N_DOC + 7) / 8, 256, 0, s_doc>>>(b1, lin_w, lin_b, out);
    cudaEventRecord(ev_dc1, s_doc);

    // layer-2 GEMMs (WAR: w2 overwrites g_twn read by doc combine L1; d2 overwrites g_tdn read by word combine L1)
    cudaStreamWaitEvent(0, ev_dc1, 0);
    gemm_tf32_kernel<<<dim3(4, (N_WORD + BM - 1) / BM), 256>>>(nullptr, 1, 2, 0, N_WORD, 128, 512);
    cudaEventRecord(ev_w2, 0);

    cudaStreamWaitEvent(s_doc, ev_wc1, 0);
    gemm_tf32_kernel<<<dim3(2, (N_DOC + BM - 1) / BM), 256, 0, s_doc>>>(nullptr, 2, 3, 1, N_DOC, 128, 256);
    cudaEventRecord(ev_d2, s_doc);

    // final combines
    cudaStreamWaitEvent(0, ev_d2, 0);
    combine_word_kernel<true><<<(N_WORD + 7) / 8, 256>>>(b2, lin_w, lin_b, out);

    cudaStreamWaitEvent(s_doc, ev_w2, 0);
    combine_doc_kernel<true><<<(N_DOC + 7) / 8, 256, 0, s_doc>>>(b2, lin_w, lin_b, out);
    cudaEventRecord(ev_ddone, s_doc);

    // join
    cudaStreamWaitEvent(0, ev_ddone, 0);
}

// round 10
// speedup vs baseline: 1.1725x; 1.1725x over previous
#include <cuda_runtime.h>
#include <cuda_fp16.h>
#include <math.h>
#include <stdint.h>

#define N_WORD 50000
#define N_DOC  10000
#define E_WW   800000
#define E_WD   320000

// ---------------- device scratch (static allocation only) ----------------
__device__ __half g_twn[(size_t)N_WORD * 384];  // [t_ww | t_wwr | t_wd] per word
__device__ float  g_tws[(size_t)N_WORD * 128];  // combined self transform (word)
__device__ __half g_tdn[(size_t)N_DOC * 128];   // t_wdr per doc
__device__ float  g_tds[(size_t)N_DOC * 128];   // self transform (doc)
__device__ float  g_xw[(size_t)N_WORD * 128];   // layer-1 word output
__device__ float  g_xd[(size_t)N_DOC * 128];    // layer-1 doc output
__device__ float  g_Bw[256 * 512];              // concat word weights  L1
__device__ float  g_Bd[256 * 256];              // concat doc weights   L1
__device__ float  g_Bw2[128 * 512];             // concat word weights  L2
__device__ float  g_Bd2[128 * 256];             // concat doc weights   L2

// CSR per relation: 0=ww, 1=wwr, 2=wd(dst=doc), 3=wdr
__device__ int g_ptr_ww[N_WORD + 1], g_ptr_wwr[N_WORD + 1], g_ptr_wdr[N_WORD + 1];
__device__ int g_ptr_wd[N_DOC + 1];
__device__ int g_cur_ww[N_WORD + 1], g_cur_wwr[N_WORD + 1], g_cur_wdr[N_WORD + 1];
__device__ int g_cur_wd[N_DOC + 1];
__device__ int g_col_ww[E_WW], g_col_wwr[E_WW], g_col_wd[E_WD], g_col_wdr[E_WD];

__device__ __forceinline__ int* cur_of(int rel) {
    switch (rel) { case 0: return g_cur_ww; case 1: return g_cur_wwr;
                   case 2: return g_cur_wd; default: return g_cur_wdr; }
}
__device__ __forceinline__ int* ptr_of(int rel) {
    switch (rel) { case 0: return g_ptr_ww; case 1: return g_ptr_wwr;
                   case 2: return g_ptr_wd; default: return g_ptr_wdr; }
}

// ---------------- CSR build ----------------
__global__ void zero_cnt_kernel() {
    int i = blockIdx.x * blockDim.x + threadIdx.x;
    if (i < N_WORD + 1) { g_cur_ww[i] = 0; g_cur_wwr[i] = 0; g_cur_wdr[i] = 0; }
    if (i < N_DOC + 1)  { g_cur_wd[i] = 0; }
}

__global__ void hist_all_kernel(const int* __restrict__ ww_dst, const int* __restrict__ wwr_dst,
                                const int* __restrict__ wd_dst, const int* __restrict__ wdr_dst) {
    const int total = 2 * E_WW + 2 * E_WD;
    for (int i = blockIdx.x * blockDim.x + threadIdx.x; i < total; i += gridDim.x * blockDim.x) {
        if (i < E_WW)                  atomicAdd(&g_cur_ww[ww_dst[i]], 1);
        else if (i < 2 * E_WW)         atomicAdd(&g_cur_wwr[wwr_dst[i - E_WW]], 1);
        else if (i < 2 * E_WW + E_WD)  atomicAdd(&g_cur_wd[wd_dst[i - 2 * E_WW]], 1);
        else                           atomicAdd(&g_cur_wdr[wdr_dst[i - 2 * E_WW - E_WD]], 1);
    }
}

__global__ void scan_all_kernel() {
    int rel = blockIdx.x;
    int n = (rel == 2) ? N_DOC : N_WORD;
    int* cnt = cur_of(rel);
    int* ptr = ptr_of(rel);
    __shared__ int sh_warp[32];
    __shared__ int sh_carry;
    if (threadIdx.x == 0) sh_carry = 0;
    __syncthreads();
    for (int base = 0; base < n; base += 1024) {
        int i = base + (int)threadIdx.x;
        int v = (i < n) ? cnt[i] : 0;
        int lane = threadIdx.x & 31, wid = threadIdx.x >> 5;
        int x = v;
        #pragma unroll
        for (int o = 1; o < 32; o <<= 1) { int y = __shfl_up_sync(0xffffffffu, x, o); if (lane >= o) x += y; }
        if (lane == 31) sh_warp[wid] = x;
        __syncthreads();
        if (wid == 0) {
            int s = sh_warp[lane];
            #pragma unroll
            for (int o = 1; o < 32; o <<= 1) { int y = __shfl_up_sync(0xffffffffu, s, o); if (lane >= o) s += y; }
            sh_warp[lane] = s;
        }
        __syncthreads();
        int pre = (wid > 0) ? sh_warp[wid - 1] : 0;
        int incl = x + pre + sh_carry;
        if (i < n) { int excl = incl - v; ptr[i] = excl; cnt[i] = excl; }
        __syncthreads();
        if (threadIdx.x == 1023) sh_carry = incl;
        __syncthreads();
    }
    if (threadIdx.x == 0) { ptr[n] = sh_carry; cnt[n] = sh_carry; }
}

__global__ void scatter_all_kernel(const int* __restrict__ ww_src, const int* __restrict__ ww_dst,
                                   const int* __restrict__ wwr_src, const int* __restrict__ wwr_dst,
                                   const int* __restrict__ wd_src, const int* __restrict__ wd_dst,
                                   const int* __restrict__ wdr_src, const int* __restrict__ wdr_dst) {
    const int total = 2 * E_WW + 2 * E_WD;
    for (int i = blockIdx.x * blockDim.x + threadIdx.x; i < total; i += gridDim.x * blockDim.x) {
        if (i < E_WW) {
            int p = atomicAdd(&g_cur_ww[ww_dst[i]], 1);  g_col_ww[p] = ww_src[i];
        } else if (i < 2 * E_WW) {
            int j = i - E_WW;
            int p = atomicAdd(&g_cur_wwr[wwr_dst[j]], 1); g_col_wwr[p] = wwr_src[j];
        } else if (i < 2 * E_WW + E_WD) {
            int j = i - 2 * E_WW;
            int p = atomicAdd(&g_cur_wd[wd_dst[j]], 1);   g_col_wd[p] = wd_src[j];
        } else {
            int j = i - 2 * E_WW - E_WD;
            int p = atomicAdd(&g_cur_wdr[wdr_dst[j]], 1); g_col_wdr[p] = wdr_src[j];
        }
    }
}

// ---------------- weight concat prep ----------------
__global__ void prep_w_kernel(const float* __restrict__ Ws, const float* __restrict__ Wn,
                              int K, int dst) {
    int i = blockIdx.x * blockDim.x + threadIdx.x;
    if (i >= K * 128) return;
    int k = i / 128, n = i % 128;
    int KN = K * 128;
    float* B = dst ? g_Bw2 : g_Bw;
    B[k * 512 + n]       = Wn[0 * KN + k * 128 + n];
    B[k * 512 + 128 + n] = Wn[1 * KN + k * 128 + n];
    B[k * 512 + 256 + n] = Wn[2 * KN + k * 128 + n];
    B[k * 512 + 384 + n] = Ws[0 * KN + k * 128 + n] + Ws[1 * KN + k * 128 + n]
                         + Ws[3 * KN + k * 128 + n];
}
__global__ void prep_d_kernel(const float* __restrict__ Ws, const float* __restrict__ Wn,
                              int K, int dst) {
    int i = blockIdx.x * blockDim.x + threadIdx.x;
    if (i >= K * 128) return;
    int k = i / 128, n = i % 128;
    int KN = K * 128;
    float* B = dst ? g_Bd2 : g_Bd;
    B[k * 256 + n]       = Wn[3 * KN + k * 128 + n];
    B[k * 256 + 128 + n] = Ws[2 * KN + k * 128 + n];
}

// ---------------- tf32 tensor-core GEMM (R6-proven version) ----------------
#define BM 128
#define BN 128
#define BK 16
#define SMP 132

__device__ __forceinline__ uint32_t f2tf32(float f) {
    uint32_t u;
    asm("cvt.rna.tf32.f32 %0, %1;" : "=r"(u) : "f"(f));
    return u;
}

// a_sel: 0 ext, 1 g_xw, 2 g_xd ; b_sel: 0 g_Bw,1 g_Bd,2 g_Bw2,3 g_Bd2 ; c_sel: 0 word,1 doc
__global__ __launch_bounds__(256) void gemm_tf32_kernel(const float* __restrict__ a_ext,
                                                        int a_sel, int b_sel, int c_sel,
                                                        int M, int K, int N) {
    const float* A = (a_sel == 0) ? a_ext : (a_sel == 1 ? (const float*)g_xw : (const float*)g_xd);
    const float* B = (b_sel == 0) ? (const float*)g_Bw : (b_sel == 1 ? (const float*)g_Bd
                    : (b_sel == 2 ? (const float*)g_Bw2 : (const float*)g_Bd2));

    __shared__ uint32_t As[BK][SMP];
    __shared__ uint32_t Bs[BK][SMP];

    const int tid = threadIdx.x;
    const int warp = tid >> 5, lane = tid & 31;
    const int g = lane >> 2, t = lane & 3;
    const int wm0 = (warp & 1) * 64;
    const int wn0 = (warp >> 1) * 32;
    const int row0 = blockIdx.y * BM, col0 = blockIdx.x * BN;

    float c[4][4][4];
    #pragma unroll
    for (int i = 0; i < 4; ++i)
        #pragma unroll
        for (int j = 0; j < 4; ++j)
            #pragma unroll
            for (int r = 0; r < 4; ++r) c[i][j][r] = 0.0f;

    const int ar = tid >> 2;
    const int ak = (tid & 3) * 4;
    const int br = tid >> 5;
    const int bc = (tid & 31) * 4;

    for (int k0 = 0; k0 < K; k0 += BK) {
        #pragma unroll
        for (int h = 0; h < 2; ++h) {
            int r = ar + h * 64;
            int gr = row0 + r;
            float4 v = make_float4(0.f, 0.f, 0.f, 0.f);
            if (gr < M) v = *reinterpret_cast<const float4*>(A + (size_t)gr * K + k0 + ak);
            As[ak + 0][r] = f2tf32(v.x);
            As[ak + 1][r] = f2tf32(v.y);
            As[ak + 2][r] = f2tf32(v.z);
            As[ak + 3][r] = f2tf32(v.w);
        }
        #pragma unroll
        for (int h = 0; h < 2; ++h) {
            int r = br + h * 8;
            float4 v = *reinterpret_cast<const float4*>(B + (size_t)(k0 + r) * N + col0 + bc);
            uint4 u;
            u.x = f2tf32(v.x); u.y = f2tf32(v.y); u.z = f2tf32(v.z); u.w = f2tf32(v.w);
            *reinterpret_cast<uint4*>(&Bs[r][bc]) = u;
        }
        __syncthreads();

        #pragma unroll
        for (int kk = 0; kk < BK; kk += 8) {
            uint32_t af[4][4], bf[4][2];
            #pragma unroll
            for (int i = 0; i < 4; ++i) {
                int r = wm0 + i * 16 + g;
                af[i][0] = As[kk + t][r];
                af[i][1] = As[kk + t][r + 8];
                af[i][2] = As[kk + t + 4][r];
                af[i][3] = As[kk + t + 4][r + 8];
            }
            #pragma unroll
            for (int j = 0; j < 4; ++j) {
                int cc = wn0 + j * 8 + g;
                bf[j][0] = Bs[kk + t][cc];
                bf[j][1] = Bs[kk + t + 4][cc];
            }
            #pragma unroll
            for (int i = 0; i < 4; ++i)
                #pragma unroll
                for (int j = 0; j < 4; ++j) {
                    asm volatile(
                        "mma.sync.aligned.m16n8k8.row.col.f32.tf32.tf32.f32 "
                        "{%0,%1,%2,%3}, {%4,%5,%6,%7}, {%8,%9}, {%0,%1,%2,%3};"
                        : "+f"(c[i][j][0]), "+f"(c[i][j][1]), "+f"(c[i][j][2]), "+f"(c[i][j][3])
                        : "r"(af[i][0]), "r"(af[i][1]), "r"(af[i][2]), "r"(af[i][3]),
                          "r"(bf[j][0]), "r"(bf[j][1]));
                }
        }
        __syncthreads();
    }

    const int self0 = (c_sel == 0) ? 384 : 128;
    __half* HN = (c_sel == 0) ? g_twn : g_tdn;
    float*  FS = (c_sel == 0) ? g_tws : g_tds;
    const int hn_stride = self0;

    #pragma unroll
    for (int i = 0; i < 4; ++i) {
        #pragma unroll
        for (int hrow = 0; hrow < 2; ++hrow) {
            int r = row0 + wm0 + i * 16 + g + hrow * 8;
            if (r >= M) continue;
            #pragma unroll
            for (int j = 0; j < 4; ++j) {
                int cc = col0 + wn0 + j * 8 + 2 * t;
                float v0 = c[i][j][hrow * 2 + 0], v1 = c[i][j][hrow * 2 + 1];
                if (cc < self0) {
                    *reinterpret_cast<__half2*>(HN + (size_t)r * hn_stride + cc) =
                        __float22half2_rn(make_float2(v0, v1));
                } else {
                    *reinterpret_cast<float2*>(FS + (size_t)r * 128 + (cc - self0)) =
                        make_float2(v0, v1);
                }
            }
        }
    }
}

// ---------------- aggregation + combine: 16B/lane, 2 edges/warp-iter, x2 unroll ----------------
__device__ __forceinline__ void add8(float* a, uint4 u) {
    __half2 h0 = *reinterpret_cast<__half2*>(&u.x);
    __half2 h1 = *reinterpret_cast<__half2*>(&u.y);
    __half2 h2 = *reinterpret_cast<__half2*>(&u.z);
    __half2 h3 = *reinterpret_cast<__half2*>(&u.w);
    float2 f0 = __half22float2(h0), f1 = __half22float2(h1);
    float2 f2 = __half22float2(h2), f3 = __half22float2(h3);
    a[0] += f0.x; a[1] += f0.y; a[2] += f1.x; a[3] += f1.y;
    a[4] += f2.x; a[5] += f2.y; a[6] += f3.x; a[7] += f3.y;
}

// half-warp per edge: lanes 0-15 take even edges, 16-31 odd; each lane loads 16B (8 halfs).
__device__ __forceinline__ void gather_rel(const __half* __restrict__ t, int stride, int base,
                                           const int* __restrict__ ptr,
                                           const int* __restrict__ col,
                                           int v, int c8, int half, float* m) {
    int beg = ptr[v], end = ptr[v + 1];
    float a[8] = {0, 0, 0, 0, 0, 0, 0, 0};
    float b[8] = {0, 0, 0, 0, 0, 0, 0, 0};
    int e = beg + half;
    for (; e + 2 < end; e += 4) {
        int s0 = col[e], s1 = col[e + 2];
        uint4 u0 = *reinterpret_cast<const uint4*>(t + (size_t)s0 * stride + base + c8);
        uint4 u1 = *reinterpret_cast<const uint4*>(t + (size_t)s1 * stride + base + c8);
        add8(a, u0); add8(b, u1);
    }
    if (e < end) {
        int s = col[e];
        uint4 u = *reinterpret_cast<const uint4*>(t + (size_t)s * stride + base + c8);
        add8(a, u);
    }
    #pragma unroll
    for (int i = 0; i < 8; ++i) a[i] += b[i];
    #pragma unroll
    for (int i = 0; i < 8; ++i) a[i] += __shfl_xor_sync(0xffffffffu, a[i], 16);
    int d = end - beg;
    float inv = 1.0f / (float)(d > 0 ? d : 1);
    #pragma unroll
    for (int i = 0; i < 8; ++i) m[i] = a[i] * inv;
}

template <bool FINAL>
__global__ void combine_word_kernel(const float* __restrict__ b,
                                    const float* __restrict__ lin_w,
                                    const float* __restrict__ lin_b,
                                    float* __restrict__ out) {
    int warp = (blockIdx.x * blockDim.x + threadIdx.x) >> 5;
    if (warp >= N_WORD) return;
    int lane = threadIdx.x & 31;
    int half = lane >> 4, sub = lane & 15;
    int c8 = sub * 8;
    int v = warp;

    float m0[8], m1[8], m3[8];
    gather_rel(g_twn, 384, 0,   g_ptr_ww,  g_col_ww,  v, c8, half, m0);
    gather_rel(g_twn, 384, 128, g_ptr_wwr, g_col_wwr, v, c8, half, m1);
    gather_rel(g_tdn, 128, 0,   g_ptr_wdr, g_col_wdr, v, c8, half, m3);

    float4 s0 = *reinterpret_cast<const float4*>(g_tws + (size_t)v * 128 + c8);
    float4 s1 = *reinterpret_cast<const float4*>(g_tws + (size_t)v * 128 + c8 + 4);
    float selfv[8] = {s0.x, s0.y, s0.z, s0.w, s1.x, s1.y, s1.z, s1.w};

    float h[8];
    #pragma unroll
    for (int i = 0; i < 8; ++i) {
        int cc = c8 + i;
        h[i] = fmaxf(selfv[i] + m0[i] + m1[i] + m3[i] + b[cc] + b[128 + cc] + b[384 + cc], 0.f);
    }

    if (!FINAL) {
        if (half == 0)
            *reinterpret_cast<float4*>(g_xw + (size_t)v * 128 + c8) =
                make_float4(h[0], h[1], h[2], h[3]);
        else
            *reinterpret_cast<float4*>(g_xw + (size_t)v * 128 + c8 + 4) =
                make_float4(h[4], h[5], h[6], h[7]);
    } else {
        float p = 0.f;
        if (half == 0) {
            float4 lw = *reinterpret_cast<const float4*>(lin_w + c8);
            p = h[0] * lw.x + h[1] * lw.y + h[2] * lw.z + h[3] * lw.w;
        } else {
            float4 lw = *reinterpret_cast<const float4*>(lin_w + c8 + 4);
            p = h[4] * lw.x + h[5] * lw.y + h[6] * lw.z + h[7] * lw.w;
        }
        #pragma unroll
        for (int o = 16; o > 0; o >>= 1) p += __shfl_down_sync(0xffffffffu, p, o);
        if (lane == 0) out[v] = 1.0f / (1.0f + expf(-(p + lin_b[0])));
    }
}

template <bool FINAL>
__global__ void combine_doc_kernel(const float* __restrict__ b,
                                   const float* __restrict__ lin_w,
                                   const float* __restrict__ lin_b,
                                   float* __restrict__ out) {
    int warp = (blockIdx.x * blockDim.x + threadIdx.x) >> 5;
    if (warp >= N_DOC) return;
    int lane = threadIdx.x & 31;
    int half = lane >> 4, sub = lane & 15;
    int c8 = sub * 8;
    int v = warp;

    float m2[8];
    gather_rel(g_twn, 384, 256, g_ptr_wd, g_col_wd, v, c8, half, m2);

    float4 s0 = *reinterpret_cast<const float4*>(g_tds + (size_t)v * 128 + c8);
    float4 s1 = *reinterpret_cast<const float4*>(g_tds + (size_t)v * 128 + c8 + 4);
    float selfv[8] = {s0.x, s0.y, s0.z, s0.w, s1.x, s1.y, s1.z, s1.w};

    float h[8];
    #pragma unroll
    for (int i = 0; i < 8; ++i) {
        int cc = c8 + i;
        h[i] = fmaxf(selfv[i] + m2[i] + b[256 + cc], 0.f);
    }

    if (!FINAL) {
        if (half == 0)
            *reinterpret_cast<float4*>(g_xd + (size_t)v * 128 + c8) =
                make_float4(h[0], h[1], h[2], h[3]);
        else
            *reinterpret_cast<float4*>(g_xd + (size_t)v * 128 + c8 + 4) =
                make_float4(h[4], h[5], h[6], h[7]);
    } else {
        float p = 0.f;
        if (half == 0) {
            float4 lw = *reinterpret_cast<const float4*>(lin_w + c8);
            p = h[0] * lw.x + h[1] * lw.y + h[2] * lw.z + h[3] * lw.w;
        } else {
            float4 lw = *reinterpret_cast<const float4*>(lin_w + c8 + 4);
            p = h[4] * lw.x + h[5] * lw.y + h[6] * lw.z + h[7] * lw.w;
        }
        #pragma unroll
        for (int o = 16; o > 0; o >>= 1) p += __shfl_down_sync(0xffffffffu, p, o);
        if (lane == 0) out[N_WORD + v] = 1.0f / (1.0f + expf(-(p + lin_b[0])));
    }
}

// ---------------- host launch ----------------
extern "C" void kernel_launch(void* const* d_in, const int* in_sizes, int n_in,
                              void* d_out, int out_size) {
    const float* x_word  = (const float*)d_in[0];
    const float* x_doc   = (const float*)d_in[1];
    const int*   ww_src  = (const int*)d_in[2];
    const int*   ww_dst  = (const int*)d_in[3];
    const int*   wwr_src = (const int*)d_in[4];
    const int*   wwr_dst = (const int*)d_in[5];
    const int*   wd_src  = (const int*)d_in[6];
    const int*   wd_dst  = (const int*)d_in[7];
    const int*   wdr_src = (const int*)d_in[8];
    const int*   wdr_dst = (const int*)d_in[9];
    const float* Wself1  = (const float*)d_in[10];
    const float* Wneigh1 = (const float*)d_in[11];
    const float* b1      = (const float*)d_in[12];
    const float* Wself2  = (const float*)d_in[13];
    const float* Wneigh2 = (const float*)d_in[14];
    const float* b2      = (const float*)d_in[15];
    const float* lin_w   = (const float*)d_in[16];
    const float* lin_b   = (const float*)d_in[17];
    float* out = (float*)d_out;

    static cudaStream_t s_csr = nullptr;
    static cudaEvent_t ev_fork = nullptr, ev_csr = nullptr, ev_prep2 = nullptr;
    if (s_csr == nullptr) {
        cudaStreamCreateWithFlags(&s_csr, cudaStreamNonBlocking);
        cudaEventCreateWithFlags(&ev_fork, cudaEventDisableTiming);
        cudaEventCreateWithFlags(&ev_csr, cudaEventDisableTiming);
        cudaEventCreateWithFlags(&ev_prep2, cudaEventDisableTiming);
    }

    // fork: CSR build + L2 weight prep on side stream, L1 GEMMs on main stream
    cudaEventRecord(ev_fork, 0);
    cudaStreamWaitEvent(s_csr, ev_fork, 0);

    zero_cnt_kernel<<<(N_WORD + 256) / 256, 256, 0, s_csr>>>();
    hist_all_kernel<<<1184, 256, 0, s_csr>>>(ww_dst, wwr_dst, wd_dst, wdr_dst);
    scan_all_kernel<<<4, 1024, 0, s_csr>>>();
    scatter_all_kernel<<<1184, 256, 0, s_csr>>>(ww_src, ww_dst, wwr_src, wwr_dst,
                                                wd_src, wd_dst, wdr_src, wdr_dst);
    cudaEventRecord(ev_csr, s_csr);
    prep_w_kernel<<<(128 * 128 + 255) / 256, 256, 0, s_csr>>>(Wself2, Wneigh2, 128, 1);
    prep_d_kernel<<<(128 * 128 + 255) / 256, 256, 0, s_csr>>>(Wself2, Wneigh2, 128, 1);
    cudaEventRecord(ev_prep2, s_csr);

    // --- layer 1 (K = 256) ---
    prep_w_kernel<<<(256 * 128 + 255) / 256, 256>>>(Wself1, Wneigh1, 256, 0);
    prep_d_kernel<<<(256 * 128 + 255) / 256, 256>>>(Wself1, Wneigh1, 256, 0);
    gemm_tf32_kernel<<<dim3(4, (N_WORD + BM - 1) / BM), 256>>>(x_word, 0, 0, 0, N_WORD, 256, 512);
    gemm_tf32_kernel<<<dim3(2, (N_DOC + BM - 1) / BM), 256>>>(x_doc, 0, 1, 1, N_DOC, 256, 256);

    cudaStreamWaitEvent(0, ev_csr, 0);
    combine_word_kernel<false><<<(N_WORD + 7) / 8, 256>>>(b1, lin_w, lin_b, out);
    combine_doc_kernel<false><<<(N_DOC + 7) / 8, 256>>>(b1, lin_w, lin_b, out);

    // --- layer 2 (K = 128) + fused final linear/sigmoid ---
    cudaStreamWaitEvent(0, ev_prep2, 0);
    gemm_tf32_kernel<<<dim3(4, (N_WORD + BM - 1) / BM), 256>>>(nullptr, 1, 2, 0, N_WORD, 128, 512);
    gemm_tf32_kernel<<<dim3(2, (N_DOC + BM - 1) / BM), 256>>>(nullptr, 2, 3, 1, N_DOC, 128, 256);
    combine_word_kernel<true><<<(N_WORD + 7) / 8, 256>>>(b2, lin_w, lin_b, out);
    combine_doc_kernel<true><<<(N_DOC + 7) / 8, 256>>>(b2, lin_w, lin_b, out);
}

// round 13
// speedup vs baseline: 1.5092x; 1.2872x over previous
#include <cuda_runtime.h>
#include <cuda_fp16.h>
#include <math.h>
#include <stdint.h>

#define N_WORD 50000
#define N_DOC  10000
#define E_WW   800000
#define E_WD   320000

// ---------------- device scratch (static allocation only) ----------------
__device__ __half g_twn[(size_t)N_WORD * 384];  // [t_ww | t_wwr | t_wd] per word
__device__ float  g_tws[(size_t)N_WORD * 128];  // combined self transform (word)
__device__ __half g_tdn[(size_t)N_DOC * 128];   // t_wdr per doc
__device__ float  g_tds[(size_t)N_DOC * 128];   // self transform (doc)
__device__ float  g_xw[(size_t)N_WORD * 128];   // layer-1 word output
__device__ float  g_xd[(size_t)N_DOC * 128];    // layer-1 doc output
// Transposed fp16 concat weights: Bt[n][k], row stride = K of current layer
__device__ __half g_Bw[512 * 256];              // word weights (max K=256)
__device__ __half g_Bd[256 * 256];              // doc weights  (max K=256)

// CSR per relation: 0=ww, 1=wwr, 2=wd(dst=doc), 3=wdr
__device__ int g_ptr_ww[N_WORD + 1], g_ptr_wwr[N_WORD + 1], g_ptr_wdr[N_WORD + 1];
__device__ int g_ptr_wd[N_DOC + 1];
__device__ int g_cur_ww[N_WORD + 1], g_cur_wwr[N_WORD + 1], g_cur_wdr[N_WORD + 1];
__device__ int g_cur_wd[N_DOC + 1];
__device__ int g_col_ww[E_WW], g_col_wwr[E_WW], g_col_wd[E_WD], g_col_wdr[E_WD];

__device__ __forceinline__ int* cur_of(int rel) {
    switch (rel) { case 0: return g_cur_ww; case 1: return g_cur_wwr;
                   case 2: return g_cur_wd; default: return g_cur_wdr; }
}
__device__ __forceinline__ int* ptr_of(int rel) {
    switch (rel) { case 0: return g_ptr_ww; case 1: return g_ptr_wwr;
                   case 2: return g_ptr_wd; default: return g_ptr_wdr; }
}

// ---------------- CSR build ----------------
__global__ void zero_cnt_kernel() {
    int i = blockIdx.x * blockDim.x + threadIdx.x;
    if (i < N_WORD + 1) { g_cur_ww[i] = 0; g_cur_wwr[i] = 0; g_cur_wdr[i] = 0; }
    if (i < N_DOC + 1)  { g_cur_wd[i] = 0; }
}

__global__ void hist_all_kernel(const int* __restrict__ ww_dst, const int* __restrict__ wwr_dst,
                                const int* __restrict__ wd_dst, const int* __restrict__ wdr_dst) {
    const int total = 2 * E_WW + 2 * E_WD;
    for (int i = blockIdx.x * blockDim.x + threadIdx.x; i < total; i += gridDim.x * blockDim.x) {
        if (i < E_WW)                  atomicAdd(&g_cur_ww[ww_dst[i]], 1);
        else if (i < 2 * E_WW)         atomicAdd(&g_cur_wwr[wwr_dst[i - E_WW]], 1);
        else if (i < 2 * E_WW + E_WD)  atomicAdd(&g_cur_wd[wd_dst[i - 2 * E_WW]], 1);
        else                           atomicAdd(&g_cur_wdr[wdr_dst[i - 2 * E_WW - E_WD]], 1);
    }
}

__global__ void scan_all_kernel() {
    int rel = blockIdx.x;
    int n = (rel == 2) ? N_DOC : N_WORD;
    int* cnt = cur_of(rel);
    int* ptr = ptr_of(rel);
    __shared__ int sh_warp[32];
    __shared__ int sh_carry;
    if (threadIdx.x == 0) sh_carry = 0;
    __syncthreads();
    for (int base = 0; base < n; base += 1024) {
        int i = base + (int)threadIdx.x;
        int v = (i < n) ? cnt[i] : 0;
        int lane = threadIdx.x & 31, wid = threadIdx.x >> 5;
        int x = v;
        #pragma unroll
        for (int o = 1; o < 32; o <<= 1) { int y = __shfl_up_sync(0xffffffffu, x, o); if (lane >= o) x += y; }
        if (lane == 31) sh_warp[wid] = x;
        __syncthreads();
        if (wid == 0) {
            int s = sh_warp[lane];
            #pragma unroll
            for (int o = 1; o < 32; o <<= 1) { int y = __shfl_up_sync(0xffffffffu, s, o); if (lane >= o) s += y; }
            sh_warp[lane] = s;
        }
        __syncthreads();
        int pre = (wid > 0) ? sh_warp[wid - 1] : 0;
        int incl = x + pre + sh_carry;
        if (i < n) { int excl = incl - v; ptr[i] = excl; cnt[i] = excl; }
        __syncthreads();
        if (threadIdx.x == 1023) sh_carry = incl;
        __syncthreads();
    }
    if (threadIdx.x == 0) { ptr[n] = sh_carry; cnt[n] = sh_carry; }
}

__global__ void scatter_all_kernel(const int* __restrict__ ww_src, const int* __restrict__ ww_dst,
                                   const int* __restrict__ wwr_src, const int* __restrict__ wwr_dst,
                                   const int* __restrict__ wd_src, const int* __restrict__ wd_dst,
                                   const int* __restrict__ wdr_src, const int* __restrict__ wdr_dst) {
    const int total = 2 * E_WW + 2 * E_WD;
    for (int i = blockIdx.x * blockDim.x + threadIdx.x; i < total; i += gridDim.x * blockDim.x) {
        if (i < E_WW) {
            int p = atomicAdd(&g_cur_ww[ww_dst[i]], 1);  g_col_ww[p] = ww_src[i];
        } else if (i < 2 * E_WW) {
            int j = i - E_WW;
            int p = atomicAdd(&g_cur_wwr[wwr_dst[j]], 1); g_col_wwr[p] = wwr_src[j];
        } else if (i < 2 * E_WW + E_WD) {
            int j = i - 2 * E_WW;
            int p = atomicAdd(&g_cur_wd[wd_dst[j]], 1);   g_col_wd[p] = wd_src[j];
        } else {
            int j = i - 2 * E_WW - E_WD;
            int p = atomicAdd(&g_cur_wdr[wdr_dst[j]], 1); g_col_wdr[p] = wdr_src[j];
        }
    }
}

// ---------------- weight concat prep: transpose to Bt[n][k], convert fp16 ----------------
__global__ void prep_w_kernel(const float* __restrict__ Ws, const float* __restrict__ Wn, int K) {
    int i = blockIdx.x * blockDim.x + threadIdx.x;
    if (i >= K * 128) return;
    int n = i / K, k = i % K;
    int KN = K * 128;
    g_Bw[(size_t)(0   + n) * K + k] = __float2half(Wn[0 * KN + k * 128 + n]);
    g_Bw[(size_t)(128 + n) * K + k] = __float2half(Wn[1 * KN + k * 128 + n]);
    g_Bw[(size_t)(256 + n) * K + k] = __float2half(Wn[2 * KN + k * 128 + n]);
    g_Bw[(size_t)(384 + n) * K + k] = __float2half(Ws[0 * KN + k * 128 + n]
                                                 + Ws[1 * KN + k * 128 + n]
                                                 + Ws[3 * KN + k * 128 + n]);
}
__global__ void prep_d_kernel(const float* __restrict__ Ws, const float* __restrict__ Wn, int K) {
    int i = blockIdx.x * blockDim.x + threadIdx.x;
    if (i >= K * 128) return;
    int n = i / K, k = i % K;
    int KN = K * 128;
    g_Bd[(size_t)(0   + n) * K + k] = __float2half(Wn[3 * KN + k * 128 + n]);
    g_Bd[(size_t)(128 + n) * K + k] = __float2half(Ws[2 * KN + k * 128 + n]);
}

// ---------------- fp16 tensor-core GEMM: C[M,N] = A[M,K] @ Bt[N,K]^T ----------------
// 128x128 block tile, BK=32, 8 warps 2(m)x4(n), warp tile 64x32, mma m16n8k16.
#define GBK 32
#define AST 40   // half stride: word-stride 20 mod 32 -> conflict-free fragments

// a_sel: 0 ext, 1 g_xw, 2 g_xd ; b_sel: 0 g_Bw, 1 g_Bd ; c_sel: 0 word, 1 doc
__global__ __launch_bounds__(256) void gemm_fp16_kernel(const float* __restrict__ a_ext,
                                                        int a_sel, int b_sel, int c_sel,
                                                        int M, int K, int N) {
    const float* A = (a_sel == 0) ? a_ext : (a_sel == 1 ? (const float*)g_xw : (const float*)g_xd);
    const __half* Bt = (b_sel == 0) ? (const __half*)g_Bw : (const __half*)g_Bd;

    __shared__ __half As[128][AST];
    __shared__ __half Bs[128][AST];

    const int tid = threadIdx.x;
    const int warp = tid >> 5, lane = tid & 31;
    const int g = lane >> 2, t = lane & 3;
    const int wm0 = (warp & 1) * 64;
    const int wn0 = (warp >> 1) * 32;
    const int row0 = blockIdx.y * 128, col0 = blockIdx.x * 128;

    float c[4][4][4];
    #pragma unroll
    for (int i = 0; i < 4; ++i)
        #pragma unroll
        for (int j = 0; j < 4; ++j)
            #pragma unroll
            for (int r = 0; r < 4; ++r) c[i][j][r] = 0.0f;

    const int srow = tid >> 1;         // 0..127
    const int scol = (tid & 1) * 16;   // 0 or 16

    for (int k0 = 0; k0 < K; k0 += GBK) {
        // stage A: 16 fp32 -> 16 fp16 per thread
        {
            int gr = row0 + srow;
            if (gr < M) {
                const float* ap = A + (size_t)gr * K + k0 + scol;
                #pragma unroll
                for (int q = 0; q < 4; ++q) {
                    float4 v = *reinterpret_cast<const float4*>(ap + 4 * q);
                    __half2 p0 = __float22half2_rn(make_float2(v.x, v.y));
                    __half2 p1 = __float22half2_rn(make_float2(v.z, v.w));
                    uint2 u;
                    u.x = *reinterpret_cast<uint32_t*>(&p0);
                    u.y = *reinterpret_cast<uint32_t*>(&p1);
                    *reinterpret_cast<uint2*>(&As[srow][scol + 4 * q]) = u;
                }
            } else {
                #pragma unroll
                for (int q = 0; q < 4; ++q)
                    *reinterpret_cast<uint2*>(&As[srow][scol + 4 * q]) = make_uint2(0u, 0u);
            }
        }
        // stage B: 16 fp16 per thread (already fp16 in global)
        {
            const __half* bp = Bt + (size_t)(col0 + srow) * K + k0 + scol;
            uint4 u0 = *reinterpret_cast<const uint4*>(bp);
            uint4 u1 = *reinterpret_cast<const uint4*>(bp + 8);
            *reinterpret_cast<uint4*>(&Bs[srow][scol])     = u0;
            *reinterpret_cast<uint4*>(&Bs[srow][scol + 8]) = u1;
        }
        __syncthreads();

        #pragma unroll
        for (int kk = 0; kk < GBK; kk += 16) {
            uint32_t af[4][4], bf[4][2];
            #pragma unroll
            for (int i = 0; i < 4; ++i) {
                int r = wm0 + i * 16 + g;
                af[i][0] = *reinterpret_cast<const uint32_t*>(&As[r][kk + 2 * t]);
                af[i][1] = *reinterpret_cast<const uint32_t*>(&As[r + 8][kk + 2 * t]);
                af[i][2] = *reinterpret_cast<const uint32_t*>(&As[r][kk + 8 + 2 * t]);
                af[i][3] = *reinterpret_cast<const uint32_t*>(&As[r + 8][kk + 8 + 2 * t]);
            }
            #pragma unroll
            for (int j = 0; j < 4; ++j) {
                int nn = wn0 + j * 8 + g;
                bf[j][0] = *reinterpret_cast<const uint32_t*>(&Bs[nn][kk + 2 * t]);
                bf[j][1] = *reinterpret_cast<const uint32_t*>(&Bs[nn][kk + 8 + 2 * t]);
            }
            #pragma unroll
            for (int i = 0; i < 4; ++i)
                #pragma unroll
                for (int j = 0; j < 4; ++j) {
                    asm volatile(
                        "mma.sync.aligned.m16n8k16.row.col.f32.f16.f16.f32 "
                        "{%0,%1,%2,%3}, {%4,%5,%6,%7}, {%8,%9}, {%0,%1,%2,%3};"
                        : "+f"(c[i][j][0]), "+f"(c[i][j][1]), "+f"(c[i][j][2]), "+f"(c[i][j][3])
                        : "r"(af[i][0]), "r"(af[i][1]), "r"(af[i][2]), "r"(af[i][3]),
                          "r"(bf[j][0]), "r"(bf[j][1]));
                }
        }
        __syncthreads();
    }

    // epilogue: split fp16 neighbor / fp32 self
    const int self0 = (c_sel == 0) ? 384 : 128;
    __half* HN = (c_sel == 0) ? g_twn : g_tdn;
    float*  FS = (c_sel == 0) ? g_tws : g_tds;
    const int hn_stride = self0;

    #pragma unroll
    for (int i = 0; i < 4; ++i) {
        #pragma unroll
        for (int hrow = 0; hrow < 2; ++hrow) {
            int r = row0 + wm0 + i * 16 + g + hrow * 8;
            if (r >= M) continue;
            #pragma unroll
            for (int j = 0; j < 4; ++j) {
                int cc = col0 + wn0 + j * 8 + 2 * t;
                float v0 = c[i][j][hrow * 2 + 0], v1 = c[i][j][hrow * 2 + 1];
                if (cc < self0) {
                    *reinterpret_cast<__half2*>(HN + (size_t)r * hn_stride + cc) =
                        __float22half2_rn(make_float2(v0, v1));
                } else {
                    *reinterpret_cast<float2*>(FS + (size_t)r * 128 + (cc - self0)) =
                        make_float2(v0, v1);
                }
            }
        }
    }
}

// ---------------- aggregation + combine (R6-proven ILP4 gather) ----------------
__device__ __forceinline__ void acc_h4(float4& acc, const __half* __restrict__ p) {
    uint2 u = *reinterpret_cast<const uint2*>(p);
    __half2 h0 = *reinterpret_cast<const __half2*>(&u.x);
    __half2 h1 = *reinterpret_cast<const __half2*>(&u.y);
    float2 a = __half22float2(h0);
    float2 b = __half22float2(h1);
    acc.x += a.x; acc.y += a.y; acc.z += b.x; acc.w += b.y;
}

__device__ __forceinline__ float4 gather_mean_h(const __half* __restrict__ t, int stride, int base,
                                                const int* __restrict__ ptr,
                                                const int* __restrict__ col, int v, int c4) {
    int beg = ptr[v], end = ptr[v + 1];
    float4 a0 = make_float4(0.f, 0.f, 0.f, 0.f);
    float4 a1 = make_float4(0.f, 0.f, 0.f, 0.f);
    float4 a2 = make_float4(0.f, 0.f, 0.f, 0.f);
    float4 a3 = make_float4(0.f, 0.f, 0.f, 0.f);
    int e = beg;
    for (; e + 4 <= end; e += 4) {
        int s0 = col[e], s1 = col[e + 1], s2 = col[e + 2], s3 = col[e + 3];
        acc_h4(a0, t + (size_t)s0 * stride + base + c4);
        acc_h4(a1, t + (size_t)s1 * stride + base + c4);
        acc_h4(a2, t + (size_t)s2 * stride + base + c4);
        acc_h4(a3, t + (size_t)s3 * stride + base + c4);
    }
    for (; e < end; ++e) {
        int s = col[e];
        acc_h4(a0, t + (size_t)s * stride + base + c4);
    }
    a0.x += a1.x + a2.x + a3.x;
    a0.y += a1.y + a2.y + a3.y;
    a0.z += a1.z + a2.z + a3.z;
    a0.w += a1.w + a2.w + a3.w;
    int d = end - beg;
    float inv = 1.0f / (float)(d > 0 ? d : 1);
    a0.x *= inv; a0.y *= inv; a0.z *= inv; a0.w *= inv;
    return a0;
}

template <bool FINAL>
__global__ void combine_word_kernel(const float* __restrict__ b,
                                    const float* __restrict__ lin_w,
                                    const float* __restrict__ lin_b,
                                    float* __restrict__ out) {
    int warp = (blockIdx.x * blockDim.x + threadIdx.x) >> 5;
    if (warp >= N_WORD) return;
    int lane = threadIdx.x & 31;
    int c4 = lane * 4;
    int v = warp;

    float4 h = *reinterpret_cast<const float4*>(g_tws + (size_t)v * 128 + c4);
    float4 m0 = gather_mean_h(g_twn, 384, 0,   g_ptr_ww,  g_col_ww,  v, c4);
    float4 m1 = gather_mean_h(g_twn, 384, 128, g_ptr_wwr, g_col_wwr, v, c4);
    float4 m3 = gather_mean_h(g_tdn, 128, 0,   g_ptr_wdr, g_col_wdr, v, c4);

    h.x = fmaxf(h.x + m0.x + m1.x + m3.x + b[c4 + 0] + b[128 + c4 + 0] + b[384 + c4 + 0], 0.f);
    h.y = fmaxf(h.y + m0.y + m1.y + m3.y + b[c4 + 1] + b[128 + c4 + 1] + b[384 + c4 + 1], 0.f);
    h.z = fmaxf(h.z + m0.z + m1.z + m3.z + b[c4 + 2] + b[128 + c4 + 2] + b[384 + c4 + 2], 0.f);
    h.w = fmaxf(h.w + m0.w + m1.w + m3.w + b[c4 + 3] + b[128 + c4 + 3] + b[384 + c4 + 3], 0.f);

    if (!FINAL) {
        *reinterpret_cast<float4*>(g_xw + (size_t)v * 128 + c4) = h;
    } else {
        float4 lw = *reinterpret_cast<const float4*>(lin_w + c4);
        float p = h.x * lw.x + h.y * lw.y + h.z * lw.z + h.w * lw.w;
        #pragma unroll
        for (int o = 16; o > 0; o >>= 1) p += __shfl_down_sync(0xffffffffu, p, o);
        if (lane == 0) out[v] = 1.0f / (1.0f + expf(-(p + lin_b[0])));
    }
}

template <bool FINAL>
__global__ void combine_doc_kernel(const float* __restrict__ b,
                                   const float* __restrict__ lin_w,
                                   const float* __restrict__ lin_b,
                                   float* __restrict__ out) {
    int warp = (blockIdx.x * blockDim.x + threadIdx.x) >> 5;
    if (warp >= N_DOC) return;
    int lane = threadIdx.x & 31;
    int c4 = lane * 4;
    int v = warp;

    float4 h = *reinterpret_cast<const float4*>(g_tds + (size_t)v * 128 + c4);
    float4 m2 = gather_mean_h(g_twn, 384, 256, g_ptr_wd, g_col_wd, v, c4);

    h.x = fmaxf(h.x + m2.x + b[256 + c4 + 0], 0.f);
    h.y = fmaxf(h.y + m2.y + b[256 + c4 + 1], 0.f);
    h.z = fmaxf(h.z + m2.z + b[256 + c4 + 2], 0.f);
    h.w = fmaxf(h.w + m2.w + b[256 + c4 + 3], 0.f);

    if (!FINAL) {
        *reinterpret_cast<float4*>(g_xd + (size_t)v * 128 + c4) = h;
    } else {
        float4 lw = *reinterpret_cast<const float4*>(lin_w + c4);
        float p = h.x * lw.x + h.y * lw.y + h.z * lw.z + h.w * lw.w;
        #pragma unroll
        for (int o = 16; o > 0; o >>= 1) p += __shfl_down_sync(0xffffffffu, p, o);
        if (lane == 0) out[N_WORD + v] = 1.0f / (1.0f + expf(-(p + lin_b[0])));
    }
}

// ---------------- host launch ----------------
extern "C" void kernel_launch(void* const* d_in, const int* in_sizes, int n_in,
                              void* d_out, int out_size) {
    const float* x_word  = (const float*)d_in[0];
    const float* x_doc   = (const float*)d_in[1];
    const int*   ww_src  = (const int*)d_in[2];
    const int*   ww_dst  = (const int*)d_in[3];
    const int*   wwr_src = (const int*)d_in[4];
    const int*   wwr_dst = (const int*)d_in[5];
    const int*   wd_src  = (const int*)d_in[6];
    const int*   wd_dst  = (const int*)d_in[7];
    const int*   wdr_src = (const int*)d_in[8];
    const int*   wdr_dst = (const int*)d_in[9];
    const float* Wself1  = (const float*)d_in[10];
    const float* Wneigh1 = (const float*)d_in[11];
    const float* b1      = (const float*)d_in[12];
    const float* Wself2  = (const float*)d_in[13];
    const float* Wneigh2 = (const float*)d_in[14];
    const float* b2      = (const float*)d_in[15];
    const float* lin_w   = (const float*)d_in[16];
    const float* lin_b   = (const float*)d_in[17];
    float* out = (float*)d_out;

    static cudaStream_t s_csr = nullptr;
    static cudaEvent_t ev_fork = nullptr, ev_csr = nullptr;
    if (s_csr == nullptr) {
        cudaStreamCreateWithFlags(&s_csr, cudaStreamNonBlocking);
        cudaEventCreateWithFlags(&ev_fork, cudaEventDisableTiming);
        cudaEventCreateWithFlags(&ev_csr, cudaEventDisableTiming);
    }

    // fork: CSR build runs on s_csr concurrently with layer-1 GEMMs on stream 0
    cudaEventRecord(ev_fork, 0);
    cudaStreamWaitEvent(s_csr, ev_fork, 0);

    zero_cnt_kernel<<<(N_WORD + 256) / 256, 256, 0, s_csr>>>();
    hist_all_kernel<<<1184, 256, 0, s_csr>>>(ww_dst, wwr_dst, wd_dst, wdr_dst);
    scan_all_kernel<<<4, 1024, 0, s_csr>>>();
    scatter_all_kernel<<<1184, 256, 0, s_csr>>>(ww_src, ww_dst, wwr_src, wwr_dst,
                                                wd_src, wd_dst, wdr_src, wdr_dst);
    cudaEventRecord(ev_csr, s_csr);

    // --- layer 1 (K = 256) ---
    prep_w_kernel<<<(256 * 128 + 255) / 256, 256>>>(Wself1, Wneigh1, 256);
    prep_d_kernel<<<(256 * 128 + 255) / 256, 256>>>(Wself1, Wneigh1, 256);
    gemm_fp16_kernel<<<dim3(4, (N_WORD + 127) / 128), 256>>>(x_word, 0, 0, 0, N_WORD, 256, 512);
    gemm_fp16_kernel<<<dim3(2, (N_DOC + 127) / 128), 256>>>(x_doc, 0, 1, 1, N_DOC, 256, 256);

    cudaStreamWaitEvent(0, ev_csr, 0);
    combine_word_kernel<false><<<(N_WORD + 7) / 8, 256>>>(b1, lin_w, lin_b, out);
    combine_doc_kernel<false><<<(N_DOC + 7) / 8, 256>>>(b1, lin_w, lin_b, out);

    // --- layer 2 (K = 128) + fused final linear/sigmoid ---
    prep_w_kernel<<<(128 * 128 + 255) / 256, 256>>>(Wself2, Wneigh2, 128);
    prep_d_kernel<<<(128 * 128 + 255) / 256, 256>>>(Wself2, Wneigh2, 128);
    gemm_fp16_kernel<<<dim3(4, (N_WORD + 127) / 128), 256>>>(nullptr, 1, 0, 0, N_WORD, 128, 512);
    gemm_fp16_kernel<<<dim3(2, (N_DOC + 127) / 128), 256>>>(nullptr, 2, 1, 1, N_DOC, 128, 256);
    combine_word_kernel<true><<<(N_WORD + 7) / 8, 256>>>(b2, lin_w, lin_b, out);
    combine_doc_kernel<true><<<(N_DOC + 7) / 8, 256>>>(b2, lin_w, lin_b, out);
}